// round 2
// baseline (speedup 1.0000x reference)
#include <cuda_runtime.h>
#include <math.h>

#define BB 512   // batch
#define TT 256   // time
#define FF 128   // features
#define HH 512   // hidden

// ---------------- scratch (__device__ globals: allocation-free) ----------------
__device__ float g_gamma_h[(size_t)TT * BB * HH];   // [t][b][H]   256 MB
__device__ float g_gamma_x[(size_t)BB * TT * FF];   // [b][t][F]    64 MB (r-major)
__device__ float g_alpha [(size_t)TT * BB * FF];    // [t][b][F]    64 MB
__device__ float g_mf    [(size_t)BB * TT * FF];    // float(masks) 64 MB
__device__ float g_h   [BB * HH];
__device__ float g_c   [BB * HH];
__device__ float g_hdec[BB * HH];

// ---------------- init: zero state, cast masks ----------------
__global__ void init_kernel(const int* __restrict__ masks) {
    int idx = blockIdx.x * blockDim.x + threadIdx.x;
    int stride = gridDim.x * blockDim.x;
    for (int i = idx; i < BB * HH; i += stride) { g_h[i] = 0.f; g_c[i] = 0.f; }
    for (size_t i = idx; i < (size_t)BB * TT * FF; i += stride)
        g_mf[i] = (float)masks[i];
}

// ---------------- precompute GEMMs (gamma_h, gamma_x, alpha) ----------------
// Rows r = b*TT + t. All A sources are r-major with row stride 128.
// MODE 0: gamma_h = exp(-relu(.)) -> g_gamma_h [t][b][N]
// MODE 1: gamma_x = exp(-relu(.)) -> g_gamma_x r-major
// MODE 2: alpha   = linear        -> g_alpha   [t][b][N], A = [gamma_x | mf], K=256
template<int MODE, int N, int K>
__global__ void pre_gemm_kernel(const float* __restrict__ A,
                                const float* __restrict__ W,
                                const float* __restrict__ bias)
{
    const int BM = 64, BN = 64, BK = 64;
    __shared__ float As[BK][BM + 1];
    __shared__ float Ws[BK][BN + 1];
    const float* baseA  = (MODE == 2) ? (const float*)g_gamma_x : A;
    const float* baseA2 = (MODE == 2) ? (const float*)g_mf      : A;

    int m0 = blockIdx.x * BM;
    int n0 = blockIdx.y * BN;
    int tid = threadIdx.x;
    int ty = tid >> 4, tx = tid & 15;
    float acc[4][4] = {};

    for (int k0 = 0; k0 < K; k0 += BK) {
        // A tile (64x64)
        #pragma unroll
        for (int v = tid; v < BM * BK / 4; v += 256) {
            int r = v >> 4; int kq = (v & 15) * 4;
            int k = k0 + kq;
            const float* src = (k < 128) ? baseA : baseA2;
            int kk = (k < 128) ? k : (k - 128);
            float4 a = *(const float4*)&src[(size_t)(m0 + r) * 128 + kk];
            As[kq + 0][r] = a.x; As[kq + 1][r] = a.y;
            As[kq + 2][r] = a.z; As[kq + 3][r] = a.w;
        }
        // W tile (64 cols x 64 k), W is [N,K] row-major
        #pragma unroll
        for (int v = tid; v < BN * BK / 4; v += 256) {
            int r = v >> 4; int kq = (v & 15) * 4;
            float4 w = *(const float4*)&W[(size_t)(n0 + r) * K + k0 + kq];
            Ws[kq + 0][r] = w.x; Ws[kq + 1][r] = w.y;
            Ws[kq + 2][r] = w.z; Ws[kq + 3][r] = w.w;
        }
        __syncthreads();
        #pragma unroll
        for (int kk = 0; kk < BK; kk++) {
            float a[4], w[4];
            #pragma unroll
            for (int i = 0; i < 4; i++) a[i] = As[kk][ty * 4 + i];
            #pragma unroll
            for (int j = 0; j < 4; j++) w[j] = Ws[kk][tx * 4 + j];
            #pragma unroll
            for (int i = 0; i < 4; i++)
                #pragma unroll
                for (int j = 0; j < 4; j++)
                    acc[i][j] += a[i] * w[j];
        }
        __syncthreads();
    }
    #pragma unroll
    for (int i = 0; i < 4; i++) {
        int m = m0 + ty * 4 + i;
        int b = m / TT, t = m % TT;
        #pragma unroll
        for (int j = 0; j < 4; j++) {
            int n = n0 + tx * 4 + j;
            float v = acc[i][j] + bias[n];
            if (MODE == 0)
                g_gamma_h[((size_t)t * BB + b) * HH + n] = expf(-fmaxf(v, 0.f));
            else if (MODE == 1)
                g_gamma_x[(size_t)m * FF + n] = expf(-fmaxf(v, 0.f));
            else
                g_alpha[((size_t)t * BB + b) * FF + n] = v;
        }
    }
}

// ---------------- per-step kernel A: decay, x_h, x_c, z_h, c_h, c_c ----------------
// One CTA = 8 full batch rows (all F columns) -> no inter-CTA dependency.
__global__ void step_a_kernel(const float* __restrict__ values,
                              const float* __restrict__ W_hr, const float* __restrict__ b_hr,
                              const float* __restrict__ W_fr, const float* __restrict__ b_fr,
                              float* __restrict__ out, int t)
{
    __shared__ float hd[8][HH];
    __shared__ float xh[8][FF];
    __shared__ float xc[8][FF];
    int tid = threadIdx.x;
    int ib0 = blockIdx.x * 8;

    // h_dec = h * gamma_h[t]; stash in smem + global (step_b needs it)
    #pragma unroll
    for (int v = tid; v < 8 * HH / 4; v += 256) {
        int i = v >> 7; int c = (v & 127) * 4;
        int row = ib0 + i;
        float4 hv = *(const float4*)&g_h[(size_t)row * HH + c];
        float4 gv = *(const float4*)&g_gamma_h[((size_t)t * BB + row) * HH + c];
        float4 o = make_float4(hv.x * gv.x, hv.y * gv.y, hv.z * gv.z, hv.w * gv.w);
        *(float4*)&hd[i][c] = o;
        *(float4*)&g_hdec[(size_t)row * HH + c] = o;
    }
    __syncthreads();

    int i  = tid >> 5;          // row within tile (0..7)
    int f0 = (tid & 31) * 4;    // 4 feature columns per thread
    int row = ib0 + i;

    // x_h = h_dec @ W_hr^T + b_hr   (K=512)
    float acc[4];
    #pragma unroll
    for (int j = 0; j < 4; j++) acc[j] = b_hr[f0 + j];
    for (int k = 0; k < HH; k += 4) {
        float4 hv = *(const float4*)&hd[i][k];
        #pragma unroll
        for (int j = 0; j < 4; j++) {
            float4 wv = __ldg((const float4*)&W_hr[(size_t)(f0 + j) * HH + k]);
            acc[j] += hv.x * wv.x + hv.y * wv.y + hv.z * wv.z + hv.w * wv.w;
        }
    }

    size_t gofs = ((size_t)row * TT + t) * FF + f0;
    float4 mv = *(const float4*)&g_mf[gofs];
    float4 xv = *(const float4*)&values[gofs];
    float m_[4] = {mv.x, mv.y, mv.z, mv.w};
    float x_[4] = {xv.x, xv.y, xv.z, xv.w};
    #pragma unroll
    for (int j = 0; j < 4; j++) {
        float xcv = m_[j] * x_[j] + (1.f - m_[j]) * acc[j];
        xh[i][f0 + j] = acc[j];
        xc[i][f0 + j] = xcv;
    }
    __syncthreads();

    // z_h = x_c @ W_fr^T + b_fr   (K=128)
    float accz[4];
    #pragma unroll
    for (int j = 0; j < 4; j++) accz[j] = b_fr[f0 + j];
    #pragma unroll
    for (int k = 0; k < FF; k += 4) {
        float4 xcv = *(const float4*)&xc[i][k];
        #pragma unroll
        for (int j = 0; j < 4; j++) {
            float4 wv = __ldg((const float4*)&W_fr[(size_t)(f0 + j) * FF + k]);
            accz[j] += xcv.x * wv.x + xcv.y * wv.y + xcv.z * wv.z + xcv.w * wv.w;
        }
    }

    // c_h = alpha*z_h + (1-alpha)*x_h ; c_c = m*x + (1-m)*c_h -> d_out
    float4 al = *(const float4*)&g_alpha[((size_t)t * BB + row) * FF + f0];
    float a_[4] = {al.x, al.y, al.z, al.w};
    float4 o;
    float cc[4];
    #pragma unroll
    for (int j = 0; j < 4; j++) {
        float ch = a_[j] * accz[j] + (1.f - a_[j]) * xh[i][f0 + j];
        cc[j] = m_[j] * x_[j] + (1.f - m_[j]) * ch;
    }
    o.x = cc[0]; o.y = cc[1]; o.z = cc[2]; o.w = cc[3];
    *(float4*)&out[gofs] = o;
}

// ---------------- per-step kernel B: gates GEMM + LSTM update ----------------
// gates = [c_c | m] @ W_ih^T + h_dec @ W_hh^T + b_ih + b_hh  (K = 768, N = 2048)
// CTA tile: 32 rows x 32 hidden units x 4 gates. Thread owns 4 rows x 1 unit x 4 gates
// -> LSTM pointwise update is thread-local.
__global__ void step_b_kernel(const float* __restrict__ out_cc,
                              const float* __restrict__ W_ih, const float* __restrict__ W_hh,
                              const float* __restrict__ b_ih, const float* __restrict__ b_hh,
                              int t)
{
    __shared__ float As[64][33];     // [k][m], 32 rows
    __shared__ float Ws[64][129];    // [k][c], 128 gate-cols
    int m0 = blockIdx.x * 32;
    int n0 = blockIdx.y * 32;
    int tid = threadIdx.x;
    int ty = tid >> 5;      // row group (0..7)
    int nl = tid & 31;      // hidden unit within tile
    float acc[4][4] = {};

    for (int kt = 0; kt < 12; kt++) {
        int k0 = kt * 64;
        // A tile: 32 x 64 virtual-K (c_c | m | h_dec)
        #pragma unroll
        for (int v = tid; v < 512; v += 256) {
            int r = v >> 4; int kq = (v & 15) * 4;
            int k = k0 + kq;
            int row = m0 + r;
            float4 a;
            if (k < 128)      a = *(const float4*)&out_cc[((size_t)row * TT + t) * FF + k];
            else if (k < 256) a = *(const float4*)&g_mf [((size_t)row * TT + t) * FF + (k - 128)];
            else              a = *(const float4*)&g_hdec[(size_t)row * HH + (k - 256)];
            As[kq + 0][r] = a.x; As[kq + 1][r] = a.y;
            As[kq + 2][r] = a.z; As[kq + 3][r] = a.w;
        }
        // W tile: 128 gate-cols x 64 k (W_ih then W_hh)
        #pragma unroll
        for (int v = tid; v < 2048; v += 256) {
            int c = v >> 4; int kq = (v & 15) * 4;
            int k = k0 + kq;
            int gcol = (c >> 5) * HH + n0 + (c & 31);
            float4 w;
            if (k < 256) w = *(const float4*)&W_ih[(size_t)gcol * (2 * FF) + k];
            else         w = *(const float4*)&W_hh[(size_t)gcol * HH + (k - 256)];
            Ws[kq + 0][c] = w.x; Ws[kq + 1][c] = w.y;
            Ws[kq + 2][c] = w.z; Ws[kq + 3][c] = w.w;
        }
        __syncthreads();
        #pragma unroll
        for (int kk = 0; kk < 64; kk++) {
            float a[4], w[4];
            #pragma unroll
            for (int i = 0; i < 4; i++) a[i] = As[kk][ty * 4 + i];
            #pragma unroll
            for (int g = 0; g < 4; g++) w[g] = Ws[kk][g * 32 + nl];
            #pragma unroll
            for (int i = 0; i < 4; i++)
                #pragma unroll
                for (int g = 0; g < 4; g++)
                    acc[i][g] += a[i] * w[g];
        }
        __syncthreads();
    }

    int n = n0 + nl;
    float bi[4];
    #pragma unroll
    for (int g = 0; g < 4; g++) bi[g] = b_ih[g * HH + n] + b_hh[g * HH + n];
    #pragma unroll
    for (int i = 0; i < 4; i++) {
        int row = m0 + ty * 4 + i;
        size_t idx = (size_t)row * HH + n;
        float ig = 1.f / (1.f + expf(-(acc[i][0] + bi[0])));
        float fg = 1.f / (1.f + expf(-(acc[i][1] + bi[1])));
        float gg = tanhf(acc[i][2] + bi[2]);
        float og = 1.f / (1.f + expf(-(acc[i][3] + bi[3])));
        float cn = fg * g_c[idx] + ig * gg;
        g_c[idx] = cn;
        g_h[idx] = og * tanhf(cn);
    }
}

// ---------------- launch ----------------
extern "C" void kernel_launch(void* const* d_in, const int* in_sizes, int n_in,
                              void* d_out, int out_size)
{
    const float* values = (const float*)d_in[0];
    const int*   masks  = (const int*)  d_in[1];
    const float* deltas = (const float*)d_in[2];
    const float* W_dh = (const float*)d_in[3];
    const float* b_dh = (const float*)d_in[4];
    const float* W_dx = (const float*)d_in[5];
    const float* b_dx = (const float*)d_in[6];
    const float* W_hr = (const float*)d_in[7];
    const float* b_hr = (const float*)d_in[8];
    const float* W_fr = (const float*)d_in[9];
    const float* b_fr = (const float*)d_in[10];
    const float* W_wc = (const float*)d_in[11];
    const float* b_wc = (const float*)d_in[12];
    const float* W_ih = (const float*)d_in[13];
    const float* W_hh = (const float*)d_in[14];
    const float* b_ih = (const float*)d_in[15];
    const float* b_hh = (const float*)d_in[16];
    float* out = (float*)d_out;

    init_kernel<<<2048, 256>>>(masks);

    // Precompute input-only tensors (hoisted out of the recurrence)
    pre_gemm_kernel<0, HH, FF>    <<<dim3((BB * TT) / 64, HH / 64), 256>>>(deltas, W_dh, b_dh);
    pre_gemm_kernel<1, FF, FF>    <<<dim3((BB * TT) / 64, FF / 64), 256>>>(deltas, W_dx, b_dx);
    pre_gemm_kernel<2, FF, 2*FF>  <<<dim3((BB * TT) / 64, FF / 64), 256>>>(deltas, W_wc, b_wc);

    // Recurrent scan: 2 kernels per step, default-stream ordered
    for (int t = 0; t < TT; t++) {
        step_a_kernel<<<BB / 8, 256>>>(values, W_hr, b_hr, W_fr, b_fr, out, t);
        step_b_kernel<<<dim3(BB / 32, HH / 32), 256>>>(out, W_ih, W_hh, b_ih, b_hh, t);
    }
}

// round 3
// speedup vs baseline: 2.6641x; 2.6641x over previous
#include <cuda_runtime.h>
#include <math.h>

#define BB 512   // batch
#define TT 256   // time
#define FF 128   // features
#define HH 512   // hidden

// ---------------- scratch (__device__ globals: allocation-free) ----------------
__device__ float g_gamma_h[(size_t)TT * BB * HH];   // [t][b][H]
__device__ float g_gamma_x[(size_t)BB * TT * FF];   // row-major (b*TT+t)
__device__ float g_alpha [(size_t)TT * BB * FF];    // [t][b][F]
__device__ float g_mf    [(size_t)BB * TT * FF];    // float(masks)
__device__ float g_h   [BB * HH];
__device__ float g_c   [BB * HH];
__device__ float g_hdec[BB * HH];

// ---------------- helpers ----------------
__device__ __forceinline__ unsigned f2tf32(float x) {
    unsigned r;
    asm("cvt.rna.tf32.f32 %0, %1;" : "=r"(r) : "f"(x));
    return r;
}
__device__ __forceinline__ void mma_tf32(float4& d,
    unsigned a0, unsigned a1, unsigned a2, unsigned a3,
    unsigned b0, unsigned b1)
{
    asm volatile(
        "mma.sync.aligned.m16n8k8.row.col.f32.tf32.tf32.f32 "
        "{%0,%1,%2,%3},{%4,%5,%6,%7},{%8,%9},{%0,%1,%2,%3};"
        : "+f"(d.x), "+f"(d.y), "+f"(d.z), "+f"(d.w)
        : "r"(a0), "r"(a1), "r"(a2), "r"(a3), "r"(b0), "r"(b1));
}
__device__ __forceinline__ float sigf(float x) { return 1.f / (1.f + __expf(-x)); }

// ---------------- init: zero state, cast masks ----------------
__global__ void init_kernel(const int* __restrict__ masks) {
    int idx = blockIdx.x * blockDim.x + threadIdx.x;
    int stride = gridDim.x * blockDim.x;
    for (int i = idx; i < BB * HH; i += stride) { g_h[i] = 0.f; g_c[i] = 0.f; }
    for (size_t i = idx; i < (size_t)BB * TT * FF; i += stride)
        g_mf[i] = (float)masks[i];
}

// ---------------- precompute GEMMs (gamma_h, gamma_x, alpha) ----------------
template<int MODE, int N, int K>
__global__ void pre_gemm_kernel(const float* __restrict__ A,
                                const float* __restrict__ W,
                                const float* __restrict__ bias)
{
    const int BM = 64, BN = 64, BK = 64;
    __shared__ float As[BK][BM + 1];
    __shared__ float Ws[BK][BN + 1];
    const float* baseA  = (MODE == 2) ? (const float*)g_gamma_x : A;
    const float* baseA2 = (MODE == 2) ? (const float*)g_mf      : A;

    int m0 = blockIdx.x * BM;
    int n0 = blockIdx.y * BN;
    int tid = threadIdx.x;
    int ty = tid >> 4, tx = tid & 15;
    float acc[4][4] = {};

    for (int k0 = 0; k0 < K; k0 += BK) {
        #pragma unroll
        for (int v = tid; v < BM * BK / 4; v += 256) {
            int r = v >> 4; int kq = (v & 15) * 4;
            int k = k0 + kq;
            const float* src = (k < 128) ? baseA : baseA2;
            int kk = (k < 128) ? k : (k - 128);
            float4 a = *(const float4*)&src[(size_t)(m0 + r) * 128 + kk];
            As[kq + 0][r] = a.x; As[kq + 1][r] = a.y;
            As[kq + 2][r] = a.z; As[kq + 3][r] = a.w;
        }
        #pragma unroll
        for (int v = tid; v < BN * BK / 4; v += 256) {
            int r = v >> 4; int kq = (v & 15) * 4;
            float4 w = *(const float4*)&W[(size_t)(n0 + r) * K + k0 + kq];
            Ws[kq + 0][r] = w.x; Ws[kq + 1][r] = w.y;
            Ws[kq + 2][r] = w.z; Ws[kq + 3][r] = w.w;
        }
        __syncthreads();
        #pragma unroll
        for (int kk = 0; kk < BK; kk++) {
            float a[4], w[4];
            #pragma unroll
            for (int i = 0; i < 4; i++) a[i] = As[kk][ty * 4 + i];
            #pragma unroll
            for (int j = 0; j < 4; j++) w[j] = Ws[kk][tx * 4 + j];
            #pragma unroll
            for (int i = 0; i < 4; i++)
                #pragma unroll
                for (int j = 0; j < 4; j++)
                    acc[i][j] += a[i] * w[j];
        }
        __syncthreads();
    }
    #pragma unroll
    for (int i = 0; i < 4; i++) {
        int m = m0 + ty * 4 + i;
        int b = m / TT, t = m % TT;
        #pragma unroll
        for (int j = 0; j < 4; j++) {
            int n = n0 + tx * 4 + j;
            float v = acc[i][j] + bias[n];
            if (MODE == 0)
                g_gamma_h[((size_t)t * BB + b) * HH + n] = expf(-fmaxf(v, 0.f));
            else if (MODE == 1)
                g_gamma_x[(size_t)m * FF + n] = expf(-fmaxf(v, 0.f));
            else
                g_alpha[((size_t)t * BB + b) * FF + n] = v;
        }
    }
}

// ---------------- per-step kernel A ----------------
// 128 CTAs x 256 thr; CTA owns 4 batch rows. Computes h_dec, x_h, x_c, z_h, c_c.
// W tiles staged in smem with coalesced LDG (lanes walk k) and conflict-free reads.
__global__ void __launch_bounds__(256, 1)
step_a_kernel(const float* __restrict__ values,
              const float* __restrict__ W_hr, const float* __restrict__ b_hr,
              const float* __restrict__ W_fr, const float* __restrict__ b_fr,
              float* __restrict__ out, int t)
{
    __shared__ float hd[4][HH];
    __shared__ float xcs[4][FF];
    __shared__ float Ws[64][129];
    int tid = threadIdx.x;
    int b0r = blockIdx.x * 4;

    // h_dec = h * gamma_h[t]
    for (int idx = tid; idx < 512; idx += 256) {
        int i = idx >> 7; int c = (idx & 127) * 4;
        int row = b0r + i;
        float4 hv = *(const float4*)&g_h[(size_t)row * HH + c];
        float4 gv = *(const float4*)&g_gamma_h[((size_t)t * BB + row) * HH + c];
        float4 o = make_float4(hv.x * gv.x, hv.y * gv.y, hv.z * gv.z, hv.w * gv.w);
        *(float4*)&hd[i][c] = o;
        *(float4*)&g_hdec[(size_t)row * HH + c] = o;
    }
    __syncthreads();

    int f  = tid & 127;     // feature column
    int r0 = (tid >> 7) * 2; // 2 rows per thread
    float acc[2] = { b_hr[f], b_hr[f] };

    // x_h = h_dec @ W_hr^T  (K = 512, 8 k-tiles of 64)
    for (int kt = 0; kt < 8; kt++) {
        int k0 = kt * 64;
        for (int idx = tid; idx < 2048; idx += 256) {
            int fr = idx >> 4; int kq = (idx & 15) * 4;
            float4 w = *(const float4*)&W_hr[(size_t)fr * HH + k0 + kq];
            Ws[kq + 0][fr] = w.x; Ws[kq + 1][fr] = w.y;
            Ws[kq + 2][fr] = w.z; Ws[kq + 3][fr] = w.w;
        }
        __syncthreads();
        #pragma unroll
        for (int kk = 0; kk < 64; kk += 4) {
            float4 h0 = *(const float4*)&hd[r0][k0 + kk];
            float4 h1 = *(const float4*)&hd[r0 + 1][k0 + kk];
            float w0 = Ws[kk][f], w1 = Ws[kk + 1][f];
            float w2 = Ws[kk + 2][f], w3 = Ws[kk + 3][f];
            acc[0] += h0.x * w0 + h0.y * w1 + h0.z * w2 + h0.w * w3;
            acc[1] += h1.x * w0 + h1.y * w1 + h1.z * w2 + h1.w * w3;
        }
        __syncthreads();
    }

    // x_c = m*x + (1-m)*x_h
    float m_[2], x_[2], xh_[2];
    size_t gofs[2];
    #pragma unroll
    for (int r = 0; r < 2; r++) {
        gofs[r] = ((size_t)(b0r + r0 + r) * TT + t) * FF + f;
        m_[r] = g_mf[gofs[r]];
        x_[r] = values[gofs[r]];
        xh_[r] = acc[r];
        xcs[r0 + r][f] = m_[r] * x_[r] + (1.f - m_[r]) * acc[r];
    }
    __syncthreads();

    // z_h = x_c @ W_fr^T  (K = 128, 2 k-tiles)
    float az[2] = { b_fr[f], b_fr[f] };
    for (int kt = 0; kt < 2; kt++) {
        int k0 = kt * 64;
        for (int idx = tid; idx < 2048; idx += 256) {
            int fr = idx >> 4; int kq = (idx & 15) * 4;
            float4 w = *(const float4*)&W_fr[(size_t)fr * FF + k0 + kq];
            Ws[kq + 0][fr] = w.x; Ws[kq + 1][fr] = w.y;
            Ws[kq + 2][fr] = w.z; Ws[kq + 3][fr] = w.w;
        }
        __syncthreads();
        #pragma unroll
        for (int kk = 0; kk < 64; kk += 4) {
            float4 x0 = *(const float4*)&xcs[r0][k0 + kk];
            float4 x1 = *(const float4*)&xcs[r0 + 1][k0 + kk];
            float w0 = Ws[kk][f], w1 = Ws[kk + 1][f];
            float w2 = Ws[kk + 2][f], w3 = Ws[kk + 3][f];
            az[0] += x0.x * w0 + x0.y * w1 + x0.z * w2 + x0.w * w3;
            az[1] += x1.x * w0 + x1.y * w1 + x1.z * w2 + x1.w * w3;
        }
        __syncthreads();
    }

    // c_h = alpha*z_h + (1-alpha)*x_h ; c_c = m*x + (1-m)*c_h
    #pragma unroll
    for (int r = 0; r < 2; r++) {
        float al = g_alpha[((size_t)t * BB + (b0r + r0 + r)) * FF + f];
        float ch = al * az[r] + (1.f - al) * xh_[r];
        out[gofs[r]] = m_[r] * x_[r] + (1.f - m_[r]) * ch;
    }
}

// ---------------- per-step kernel B: tf32 mma gates GEMM + fused LSTM ----------------
// gates[m, gcol] = [c_c | m | h_dec] @ [W_ih | W_hh]^T,  M=512, N=2048, K=768.
// CTA tile: 64 m x 32 units x 4 gates (128 gate-cols); grid (8, 16) = 128 CTAs.
// Warp tile: 32m x 32c via mma.m16n8k8 tf32. K staged in chunks of 32.
__global__ void __launch_bounds__(256, 1)
step_b_kernel(const float* __restrict__ out_cc,
              const float* __restrict__ W_ih, const float* __restrict__ W_hh,
              const float* __restrict__ b_ih, const float* __restrict__ b_hh,
              int t)
{
    // union: [As 64x36 | Bs 32x132] (6528 u32)  /  Gs 64x129 (8256 f32)
    __shared__ unsigned sm_u[64 * 129];
    unsigned* As = sm_u;                 // [m][k] pad 36
    unsigned* Bs = sm_u + 64 * 36;       // [k][c] pad 132
    float*    Gs = (float*)sm_u;         // epilogue alias [m][c] pad 129

    int tid  = threadIdx.x;
    int wid  = tid >> 5;
    int lane = tid & 31;
    int gID  = lane >> 2;   // 0..7
    int tg   = lane & 3;    // 0..3
    int wm   = wid >> 2;    // 0..1  (32-row group)
    int wc   = wid & 3;     // 0..3  (32-col group)
    int m0   = blockIdx.x * 64;
    int n0   = blockIdx.y * 32;

    float4 acc[2][4];
    #pragma unroll
    for (int i = 0; i < 2; i++)
        #pragma unroll
        for (int j = 0; j < 4; j++)
            acc[i][j] = make_float4(0.f, 0.f, 0.f, 0.f);

    for (int kc = 0; kc < 24; kc++) {
        // stage A: 64 rows x 32 k  (512 float4, 2 per thread)
        #pragma unroll
        for (int it = 0; it < 2; it++) {
            int idx = tid + it * 256;
            int m = idx >> 3; int kq = (idx & 7) * 4;
            int row = m0 + m;
            float4 a;
            if (kc < 4)
                a = *(const float4*)&out_cc[((size_t)row * TT + t) * FF + kc * 32 + kq];
            else if (kc < 8)
                a = *(const float4*)&g_mf[((size_t)row * TT + t) * FF + (kc - 4) * 32 + kq];
            else
                a = *(const float4*)&g_hdec[(size_t)row * HH + (kc - 8) * 32 + kq];
            uint4 u = make_uint4(f2tf32(a.x), f2tf32(a.y), f2tf32(a.z), f2tf32(a.w));
            *(uint4*)&As[m * 36 + kq] = u;
        }
        // stage B: 128 gate-cols x 32 k  (1024 float4, 4 per thread), store [k][c]
        #pragma unroll
        for (int it = 0; it < 4; it++) {
            int idx = tid + it * 256;
            int c = idx >> 3; int kq = (idx & 7) * 4;
            int gcol = (c >> 5) * HH + n0 + (c & 31);
            int k = kc * 32 + kq;
            float4 w;
            if (k < 256) w = *(const float4*)&W_ih[(size_t)gcol * 256 + k];
            else         w = *(const float4*)&W_hh[(size_t)gcol * HH + (k - 256)];
            Bs[(kq + 0) * 132 + c] = f2tf32(w.x);
            Bs[(kq + 1) * 132 + c] = f2tf32(w.y);
            Bs[(kq + 2) * 132 + c] = f2tf32(w.z);
            Bs[(kq + 3) * 132 + c] = f2tf32(w.w);
        }
        __syncthreads();
        #pragma unroll
        for (int k8 = 0; k8 < 4; k8++) {
            int kk = k8 * 8;
            unsigned a[2][4];
            #pragma unroll
            for (int mf = 0; mf < 2; mf++) {
                int r = wm * 32 + mf * 16 + gID;
                a[mf][0] = As[(r    ) * 36 + kk + tg];
                a[mf][1] = As[(r + 8) * 36 + kk + tg];
                a[mf][2] = As[(r    ) * 36 + kk + tg + 4];
                a[mf][3] = As[(r + 8) * 36 + kk + tg + 4];
            }
            #pragma unroll
            for (int nf = 0; nf < 4; nf++) {
                int c = wc * 32 + nf * 8 + gID;
                unsigned b0 = Bs[(kk + tg    ) * 132 + c];
                unsigned b1 = Bs[(kk + tg + 4) * 132 + c];
                mma_tf32(acc[0][nf], a[0][0], a[0][1], a[0][2], a[0][3], b0, b1);
                mma_tf32(acc[1][nf], a[1][0], a[1][1], a[1][2], a[1][3], b0, b1);
            }
        }
        __syncthreads();
    }

    // exchange gates through smem so each thread sees i,f,g,o for its (m, unit)
    #pragma unroll
    for (int mf = 0; mf < 2; mf++) {
        int rbase = wm * 32 + mf * 16 + gID;
        #pragma unroll
        for (int nf = 0; nf < 4; nf++) {
            int cbase = wc * 32 + nf * 8 + tg * 2;
            Gs[(rbase    ) * 129 + cbase    ] = acc[mf][nf].x;
            Gs[(rbase    ) * 129 + cbase + 1] = acc[mf][nf].y;
            Gs[(rbase + 8) * 129 + cbase    ] = acc[mf][nf].z;
            Gs[(rbase + 8) * 129 + cbase + 1] = acc[mf][nf].w;
        }
    }
    __syncthreads();

    // fused LSTM pointwise update
    int u  = tid & 31;
    int n  = n0 + u;
    float bi0 = b_ih[0 * HH + n] + b_hh[0 * HH + n];
    float bi1 = b_ih[1 * HH + n] + b_hh[1 * HH + n];
    float bi2 = b_ih[2 * HH + n] + b_hh[2 * HH + n];
    float bi3 = b_ih[3 * HH + n] + b_hh[3 * HH + n];
    #pragma unroll
    for (int j = 0; j < 8; j++) {
        int ml = (tid >> 5) + 8 * j;
        float ig = sigf(Gs[ml * 129 +  0 + u] + bi0);
        float fg = sigf(Gs[ml * 129 + 32 + u] + bi1);
        float gg = tanhf(Gs[ml * 129 + 64 + u] + bi2);
        float og = sigf(Gs[ml * 129 + 96 + u] + bi3);
        size_t idx = (size_t)(m0 + ml) * HH + n;
        float cn = fg * g_c[idx] + ig * gg;
        g_c[idx] = cn;
        g_h[idx] = og * tanhf(cn);
    }
}

// ---------------- launch ----------------
extern "C" void kernel_launch(void* const* d_in, const int* in_sizes, int n_in,
                              void* d_out, int out_size)
{
    const float* values = (const float*)d_in[0];
    const int*   masks  = (const int*)  d_in[1];
    const float* deltas = (const float*)d_in[2];
    const float* W_dh = (const float*)d_in[3];
    const float* b_dh = (const float*)d_in[4];
    const float* W_dx = (const float*)d_in[5];
    const float* b_dx = (const float*)d_in[6];
    const float* W_hr = (const float*)d_in[7];
    const float* b_hr = (const float*)d_in[8];
    const float* W_fr = (const float*)d_in[9];
    const float* b_fr = (const float*)d_in[10];
    const float* W_wc = (const float*)d_in[11];
    const float* b_wc = (const float*)d_in[12];
    const float* W_ih = (const float*)d_in[13];
    const float* W_hh = (const float*)d_in[14];
    const float* b_ih = (const float*)d_in[15];
    const float* b_hh = (const float*)d_in[16];
    float* out = (float*)d_out;

    init_kernel<<<2048, 256>>>(masks);

    pre_gemm_kernel<0, HH, FF>   <<<dim3((BB * TT) / 64, HH / 64), 256>>>(deltas, W_dh, b_dh);
    pre_gemm_kernel<1, FF, FF>   <<<dim3((BB * TT) / 64, FF / 64), 256>>>(deltas, W_dx, b_dx);
    pre_gemm_kernel<2, FF, 2*FF> <<<dim3((BB * TT) / 64, FF / 64), 256>>>(deltas, W_wc, b_wc);

    for (int t = 0; t < TT; t++) {
        step_a_kernel<<<BB / 4, 256>>>(values, W_hr, b_hr, W_fr, b_fr, out, t);
        step_b_kernel<<<dim3(BB / 64, HH / 32), 256>>>(out, W_ih, W_hh, b_ih, b_hh, t);
    }
}

// round 4
// speedup vs baseline: 4.0490x; 1.5198x over previous
#include <cuda_runtime.h>
#include <math.h>

#define BB 512   // batch
#define TT 256   // time
#define FF 128   // features
#define HH 512   // hidden

// ---------------- scratch (__device__ globals: allocation-free) ----------------
__device__ float g_gamma_h[(size_t)TT * BB * HH];   // [t][b][H]
__device__ float g_gamma_x[(size_t)BB * TT * FF];   // row-major (b*TT+t)
__device__ float g_alpha [(size_t)TT * BB * FF];    // [t][b][F]
__device__ float g_mf    [(size_t)BB * TT * FF];    // float(masks)
__device__ float g_h   [BB * HH];
__device__ float g_c   [BB * HH];
__device__ float g_hdec[BB * HH];
// Pre-packed gates weights, tf32, mma-fragment order:
// index ((ny*16 + c8)*96 + k8)*32 + lane  -> uint2 {b0, b1}
__device__ uint2 g_Bpack[16 * 16 * 96 * 32];

// ---------------- helpers ----------------
__device__ __forceinline__ unsigned f2tf32(float x) {
    unsigned r;
    asm("cvt.rna.tf32.f32 %0, %1;" : "=r"(r) : "f"(x));
    return r;
}
__device__ __forceinline__ void mma_tf32(float4& d,
    unsigned a0, unsigned a1, unsigned a2, unsigned a3,
    unsigned b0, unsigned b1)
{
    asm volatile(
        "mma.sync.aligned.m16n8k8.row.col.f32.tf32.tf32.f32 "
        "{%0,%1,%2,%3},{%4,%5,%6,%7},{%8,%9},{%0,%1,%2,%3};"
        : "+f"(d.x), "+f"(d.y), "+f"(d.z), "+f"(d.w)
        : "r"(a0), "r"(a1), "r"(a2), "r"(a3), "r"(b0), "r"(b1));
}
__device__ __forceinline__ float sigf(float x) { return 1.f / (1.f + __expf(-x)); }

// ---------------- init: zero state, cast masks ----------------
__global__ void init_kernel(const int* __restrict__ masks) {
    int idx = blockIdx.x * blockDim.x + threadIdx.x;
    int stride = gridDim.x * blockDim.x;
    for (int i = idx; i < BB * HH; i += stride) { g_h[i] = 0.f; g_c[i] = 0.f; }
    for (size_t i = idx; i < (size_t)BB * TT * FF; i += stride)
        g_mf[i] = (float)masks[i];
}

// ---------------- pack gates weights into fragment layout ----------------
// Virtual B matrix: W[gcol][k], gcol in [0,2048), k in [0,768):
//   k < 256 -> W_ih[gcol][k], else W_hh[gcol][k-256].
// Fragment entry (ny, c8, k8, lane): gID=lane>>2, tg=lane&3;
//   c = c8*8 + gID (in [0,128) within CTA tile), gcol = (c>>5)*HH + ny*32 + (c&31)
//   b0 = W[gcol][k8*8+tg], b1 = W[gcol][k8*8+tg+4]
__global__ void pack_b_kernel(const float* __restrict__ W_ih,
                              const float* __restrict__ W_hh)
{
    int idx = blockIdx.x * blockDim.x + threadIdx.x;   // < 786432
    int lane = idx & 31;
    int k8   = (idx >> 5) % 96;
    int c8   = ((idx >> 5) / 96) & 15;
    int ny   = (idx >> 5) / (96 * 16);
    int gID = lane >> 2, tg = lane & 3;
    int c = c8 * 8 + gID;
    int gcol = (c >> 5) * HH + ny * 32 + (c & 31);
    int k0 = k8 * 8 + tg;
    float w0, w1;
    if (k0 < 256) {
        w0 = W_ih[(size_t)gcol * 256 + k0];
        w1 = W_ih[(size_t)gcol * 256 + k0 + 4];
    } else {
        w0 = W_hh[(size_t)gcol * HH + (k0 - 256)];
        w1 = W_hh[(size_t)gcol * HH + (k0 - 252)];
    }
    g_Bpack[idx] = make_uint2(f2tf32(w0), f2tf32(w1));
}

// ---------------- precompute GEMMs (gamma_h, gamma_x, alpha) ----------------
template<int MODE, int N, int K>
__global__ void pre_gemm_kernel(const float* __restrict__ A,
                                const float* __restrict__ W,
                                const float* __restrict__ bias)
{
    const int BM = 64, BN = 64, BK = 64;
    __shared__ float As[BK][BM + 1];
    __shared__ float Ws[BK][BN + 1];
    const float* baseA  = (MODE == 2) ? (const float*)g_gamma_x : A;
    const float* baseA2 = (MODE == 2) ? (const float*)g_mf      : A;

    int m0 = blockIdx.x * BM;
    int n0 = blockIdx.y * BN;
    int tid = threadIdx.x;
    int ty = tid >> 4, tx = tid & 15;
    float acc[4][4] = {};

    for (int k0 = 0; k0 < K; k0 += BK) {
        #pragma unroll
        for (int v = tid; v < BM * BK / 4; v += 256) {
            int r = v >> 4; int kq = (v & 15) * 4;
            int k = k0 + kq;
            const float* src = (k < 128) ? baseA : baseA2;
            int kk = (k < 128) ? k : (k - 128);
            float4 a = *(const float4*)&src[(size_t)(m0 + r) * 128 + kk];
            As[kq + 0][r] = a.x; As[kq + 1][r] = a.y;
            As[kq + 2][r] = a.z; As[kq + 3][r] = a.w;
        }
        #pragma unroll
        for (int v = tid; v < BN * BK / 4; v += 256) {
            int r = v >> 4; int kq = (v & 15) * 4;
            float4 w = *(const float4*)&W[(size_t)(n0 + r) * K + k0 + kq];
            Ws[kq + 0][r] = w.x; Ws[kq + 1][r] = w.y;
            Ws[kq + 2][r] = w.z; Ws[kq + 3][r] = w.w;
        }
        __syncthreads();
        #pragma unroll
        for (int kk = 0; kk < BK; kk++) {
            float a[4], w[4];
            #pragma unroll
            for (int i = 0; i < 4; i++) a[i] = As[kk][ty * 4 + i];
            #pragma unroll
            for (int j = 0; j < 4; j++) w[j] = Ws[kk][tx * 4 + j];
            #pragma unroll
            for (int i = 0; i < 4; i++)
                #pragma unroll
                for (int j = 0; j < 4; j++)
                    acc[i][j] += a[i] * w[j];
        }
        __syncthreads();
    }
    #pragma unroll
    for (int i = 0; i < 4; i++) {
        int m = m0 + ty * 4 + i;
        int b = m / TT, t = m % TT;
        #pragma unroll
        for (int j = 0; j < 4; j++) {
            int n = n0 + tx * 4 + j;
            float v = acc[i][j] + bias[n];
            if (MODE == 0)
                g_gamma_h[((size_t)t * BB + b) * HH + n] = expf(-fmaxf(v, 0.f));
            else if (MODE == 1)
                g_gamma_x[(size_t)m * FF + n] = expf(-fmaxf(v, 0.f));
            else
                g_alpha[((size_t)t * BB + b) * FF + n] = v;
        }
    }
}

// ---------------- per-step kernel A ----------------
// 128 CTAs x 256 thr; CTA owns 4 batch rows.
// W tiles staged as Ws[f][k] (pad 68): inner loop = 1 LDS.128(W) + 2 broadcast per 8 FMA.
__global__ void __launch_bounds__(256, 1)
step_a_kernel(const float* __restrict__ values,
              const float* __restrict__ W_hr, const float* __restrict__ b_hr,
              const float* __restrict__ W_fr, const float* __restrict__ b_fr,
              float* __restrict__ out, int t)
{
    __shared__ float hd[4][HH];
    __shared__ float xcs[4][FF];
    __shared__ float Ws[128 * 68];
    int tid = threadIdx.x;
    int b0r = blockIdx.x * 4;

    // h_dec = h * gamma_h[t]
    for (int idx = tid; idx < 512; idx += 256) {
        int i = idx >> 7; int c = (idx & 127) * 4;
        int row = b0r + i;
        float4 hv = *(const float4*)&g_h[(size_t)row * HH + c];
        float4 gv = *(const float4*)&g_gamma_h[((size_t)t * BB + row) * HH + c];
        float4 o = make_float4(hv.x * gv.x, hv.y * gv.y, hv.z * gv.z, hv.w * gv.w);
        *(float4*)&hd[i][c] = o;
        *(float4*)&g_hdec[(size_t)row * HH + c] = o;
    }
    __syncthreads();

    int f  = tid & 127;
    int r0 = (tid >> 7) * 2;
    float acc0 = b_hr[f], acc1 = acc0;

    // x_h = h_dec @ W_hr^T  (K = 512, 8 k-tiles of 64)
    for (int kt = 0; kt < 8; kt++) {
        int k0 = kt * 64;
        #pragma unroll
        for (int it = 0; it < 8; it++) {
            int idx = tid + it * 256;
            int fr = idx >> 4; int kq = (idx & 15) * 4;
            *(float4*)&Ws[fr * 68 + kq] = *(const float4*)&W_hr[(size_t)fr * HH + k0 + kq];
        }
        __syncthreads();
        #pragma unroll
        for (int kk = 0; kk < 64; kk += 4) {
            float4 wv = *(const float4*)&Ws[f * 68 + kk];
            float4 h0 = *(const float4*)&hd[r0][k0 + kk];
            float4 h1 = *(const float4*)&hd[r0 + 1][k0 + kk];
            acc0 += h0.x * wv.x + h0.y * wv.y + h0.z * wv.z + h0.w * wv.w;
            acc1 += h1.x * wv.x + h1.y * wv.y + h1.z * wv.z + h1.w * wv.w;
        }
        __syncthreads();
    }

    // x_c = m*x + (1-m)*x_h
    float m_[2], x_[2], xh_[2];
    size_t gofs[2];
    {
        float a01[2] = {acc0, acc1};
        #pragma unroll
        for (int r = 0; r < 2; r++) {
            gofs[r] = ((size_t)(b0r + r0 + r) * TT + t) * FF + f;
            m_[r] = g_mf[gofs[r]];
            x_[r] = values[gofs[r]];
            xh_[r] = a01[r];
            xcs[r0 + r][f] = m_[r] * x_[r] + (1.f - m_[r]) * a01[r];
        }
    }
    __syncthreads();

    // z_h = x_c @ W_fr^T  (K = 128, 2 k-tiles)
    float az0 = b_fr[f], az1 = az0;
    for (int kt = 0; kt < 2; kt++) {
        int k0 = kt * 64;
        #pragma unroll
        for (int it = 0; it < 8; it++) {
            int idx = tid + it * 256;
            int fr = idx >> 4; int kq = (idx & 15) * 4;
            *(float4*)&Ws[fr * 68 + kq] = *(const float4*)&W_fr[(size_t)fr * FF + k0 + kq];
        }
        __syncthreads();
        #pragma unroll
        for (int kk = 0; kk < 64; kk += 4) {
            float4 wv = *(const float4*)&Ws[f * 68 + kk];
            float4 x0 = *(const float4*)&xcs[r0][k0 + kk];
            float4 x1 = *(const float4*)&xcs[r0 + 1][k0 + kk];
            az0 += x0.x * wv.x + x0.y * wv.y + x0.z * wv.z + x0.w * wv.w;
            az1 += x1.x * wv.x + x1.y * wv.y + x1.z * wv.z + x1.w * wv.w;
        }
        __syncthreads();
    }

    // c_h = alpha*z_h + (1-alpha)*x_h ; c_c = m*x + (1-m)*c_h
    {
        float az[2] = {az0, az1};
        #pragma unroll
        for (int r = 0; r < 2; r++) {
            float al = g_alpha[((size_t)t * BB + (b0r + r0 + r)) * FF + f];
            float ch = al * az[r] + (1.f - al) * xh_[r];
            out[gofs[r]] = m_[r] * x_[r] + (1.f - m_[r]) * ch;
        }
    }
}

// ---------------- per-step kernel B: tf32 mma gates GEMM + fused LSTM ----------------
// B fragments come straight from g_Bpack (L2-resident) via LDG -> registers.
// A staged in smem as 64-k double-buffered chunks (tf32 u32, pad 68).
__device__ __forceinline__ void stage_a_chunk(
    unsigned* __restrict__ buf, const float* __restrict__ out_cc,
    int kc, int m0, int t, int tid)
{
    int kbase = kc * 64;
    #pragma unroll
    for (int it = 0; it < 4; it++) {
        int idx = tid + it * 256;
        int m = idx >> 4; int kq = (idx & 15) * 4;
        int row = m0 + m;
        int k = kbase + kq;
        float4 a;
        if (kc < 2)
            a = *(const float4*)&out_cc[((size_t)row * TT + t) * FF + k];
        else if (kc < 4)
            a = *(const float4*)&g_mf[((size_t)row * TT + t) * FF + (k - 128)];
        else
            a = *(const float4*)&g_hdec[(size_t)row * HH + (k - 256)];
        uint4 u = make_uint4(f2tf32(a.x), f2tf32(a.y), f2tf32(a.z), f2tf32(a.w));
        *(uint4*)&buf[m * 68 + kq] = u;
    }
}

__global__ void __launch_bounds__(256, 1)
step_b_kernel(const float* __restrict__ out_cc,
              const float* __restrict__ b_ih, const float* __restrict__ b_hh,
              int t)
{
    __shared__ unsigned sm_u[2 * 64 * 68];   // double-buffered A; epilogue alias
    float* Gs = (float*)sm_u;                // [m][c] pad 129 (needs 33KB <= 34.8KB)

    int tid  = threadIdx.x;
    int wid  = tid >> 5;
    int lane = tid & 31;
    int gID  = lane >> 2;
    int tg   = lane & 3;
    int wm   = wid >> 2;    // 0..1
    int wc   = wid & 3;     // 0..3
    int m0   = blockIdx.x * 64;
    int ny   = blockIdx.y;
    int n0   = ny * 32;

    float4 acc[2][4];
    #pragma unroll
    for (int i = 0; i < 2; i++)
        #pragma unroll
        for (int j = 0; j < 4; j++)
            acc[i][j] = make_float4(0.f, 0.f, 0.f, 0.f);

    stage_a_chunk(sm_u, out_cc, 0, m0, t, tid);
    __syncthreads();

    #pragma unroll 1
    for (int kc = 0; kc < 12; kc++) {
        const unsigned* As = sm_u + (kc & 1) * (64 * 68);

        // B fragments for this chunk: 32 independent LDG.64 from packed buffer
        uint2 bf[8][4];
        {
            const uint2* bp = &g_Bpack[(((size_t)ny * 16 + wc * 4) * 96 + kc * 8) * 32 + lane];
            #pragma unroll
            for (int nf = 0; nf < 4; nf++)
                #pragma unroll
                for (int k8 = 0; k8 < 8; k8++)
                    bf[k8][nf] = __ldg(&bp[((size_t)nf * 96 + k8) * 32]);
        }

        if (kc < 11)
            stage_a_chunk(sm_u + ((kc + 1) & 1) * (64 * 68), out_cc, kc + 1, m0, t, tid);

        #pragma unroll
        for (int k8 = 0; k8 < 8; k8++) {
            int kk = k8 * 8;
            unsigned a[2][4];
            #pragma unroll
            for (int mf = 0; mf < 2; mf++) {
                int r = wm * 32 + mf * 16 + gID;
                a[mf][0] = As[(r    ) * 68 + kk + tg];
                a[mf][1] = As[(r + 8) * 68 + kk + tg];
                a[mf][2] = As[(r    ) * 68 + kk + tg + 4];
                a[mf][3] = As[(r + 8) * 68 + kk + tg + 4];
            }
            #pragma unroll
            for (int nf = 0; nf < 4; nf++) {
                mma_tf32(acc[0][nf], a[0][0], a[0][1], a[0][2], a[0][3],
                         bf[k8][nf].x, bf[k8][nf].y);
                mma_tf32(acc[1][nf], a[1][0], a[1][1], a[1][2], a[1][3],
                         bf[k8][nf].x, bf[k8][nf].y);
            }
        }
        __syncthreads();
    }

    // exchange gates through smem so each thread sees i,f,g,o for its (m, unit)
    #pragma unroll
    for (int mf = 0; mf < 2; mf++) {
        int rbase = wm * 32 + mf * 16 + gID;
        #pragma unroll
        for (int nf = 0; nf < 4; nf++) {
            int cbase = wc * 32 + nf * 8 + tg * 2;
            Gs[(rbase    ) * 129 + cbase    ] = acc[mf][nf].x;
            Gs[(rbase    ) * 129 + cbase + 1] = acc[mf][nf].y;
            Gs[(rbase + 8) * 129 + cbase    ] = acc[mf][nf].z;
            Gs[(rbase + 8) * 129 + cbase + 1] = acc[mf][nf].w;
        }
    }
    __syncthreads();

    // fused LSTM pointwise update
    int u  = tid & 31;
    int n  = n0 + u;
    float bi0 = b_ih[0 * HH + n] + b_hh[0 * HH + n];
    float bi1 = b_ih[1 * HH + n] + b_hh[1 * HH + n];
    float bi2 = b_ih[2 * HH + n] + b_hh[2 * HH + n];
    float bi3 = b_ih[3 * HH + n] + b_hh[3 * HH + n];
    #pragma unroll
    for (int j = 0; j < 8; j++) {
        int ml = (tid >> 5) + 8 * j;
        float ig = sigf(Gs[ml * 129 +  0 + u] + bi0);
        float fg = sigf(Gs[ml * 129 + 32 + u] + bi1);
        float gg = tanhf(Gs[ml * 129 + 64 + u] + bi2);
        float og = sigf(Gs[ml * 129 + 96 + u] + bi3);
        size_t idx = (size_t)(m0 + ml) * HH + n;
        float cn = fg * g_c[idx] + ig * gg;
        g_c[idx] = cn;
        g_h[idx] = og * tanhf(cn);
    }
}

// ---------------- launch ----------------
extern "C" void kernel_launch(void* const* d_in, const int* in_sizes, int n_in,
                              void* d_out, int out_size)
{
    const float* values = (const float*)d_in[0];
    const int*   masks  = (const int*)  d_in[1];
    const float* deltas = (const float*)d_in[2];
    const float* W_dh = (const float*)d_in[3];
    const float* b_dh = (const float*)d_in[4];
    const float* W_dx = (const float*)d_in[5];
    const float* b_dx = (const float*)d_in[6];
    const float* W_hr = (const float*)d_in[7];
    const float* b_hr = (const float*)d_in[8];
    const float* W_fr = (const float*)d_in[9];
    const float* b_fr = (const float*)d_in[10];
    const float* W_wc = (const float*)d_in[11];
    const float* b_wc = (const float*)d_in[12];
    const float* W_ih = (const float*)d_in[13];
    const float* W_hh = (const float*)d_in[14];
    const float* b_ih = (const float*)d_in[15];
    const float* b_hh = (const float*)d_in[16];
    float* out = (float*)d_out;

    init_kernel<<<2048, 256>>>(masks);
    pack_b_kernel<<<3072, 256>>>(W_ih, W_hh);

    pre_gemm_kernel<0, HH, FF>   <<<dim3((BB * TT) / 64, HH / 64), 256>>>(deltas, W_dh, b_dh);
    pre_gemm_kernel<1, FF, FF>   <<<dim3((BB * TT) / 64, FF / 64), 256>>>(deltas, W_dx, b_dx);
    pre_gemm_kernel<2, FF, 2*FF> <<<dim3((BB * TT) / 64, FF / 64), 256>>>(deltas, W_wc, b_wc);

    for (int t = 0; t < TT; t++) {
        step_a_kernel<<<BB / 4, 256>>>(values, W_hr, b_hr, W_fr, b_fr, out, t);
        step_b_kernel<<<dim3(BB / 64, HH / 32), 256>>>(out, b_ih, b_hh, t);
    }
}